// round 16
// baseline (speedup 1.0000x reference)
#include <cuda_runtime.h>
#include <cuda_fp16.h>
#include <cstring>

#define NN 20000      // nodes
#define NE 160000     // edges
#define TE 320000     // 2E edge-rows
#define HH 128

// ---------------- scratch (static __device__, no allocs) ----------------
__device__ __align__(128) __half s_a0  [(size_t)NN * 128];   // nr @ W0
__device__ __align__(128) __half s_a1  [(size_t)NN * 128];   // nr @ W1
__device__ __align__(128) __half s_pre1[(size_t)TE * 128];   // lvl1 pre-act
__device__ __align__(128) __half s_nin [(size_t)NN * 128];
__device__ __align__(128) __half s_np1 [(size_t)NN * 256];
__device__ __align__(128) __half s_np2 [(size_t)NN * 128];   // final pre-act (half)
__device__ __align__(128) __half s_ein [(size_t)TE * 256];
__device__ __align__(128) __half s_ep1 [(size_t)TE * 256];
__device__ __align__(128) __half s_ep2 [(size_t)TE * 128];   // final pre-act (half)
// fp16 weights, pre-transposed to n-major [N][K]
__device__ __align__(128) __half w_np1h[256 * 128];
__device__ __align__(128) __half w_np2h[128 * 256];
__device__ __align__(128) __half w_ep1h[256 * 256];
__device__ __align__(128) __half w_ep2h[128 * 256];
__device__ __align__(128) __half w_l1h [3 * 128 * 128];   // lvl1 W blocks 0,1,2 n-major
// CSR: node -> incident edge-rows
__device__ int s_deg[NN];
__device__ int s_rowptr[NN + 1];
__device__ int s_cursor[NN];
__device__ int s_csr[TE];
__device__ float s_sum[5 * 256];
__device__ float s_sq [5 * 256];
__device__ int   s_u[NE];
__device__ int   s_v[NE];
__device__ int   g_is64;

// ---------------- helpers ----------------
__device__ __forceinline__ unsigned h2u(__half2 h) {
    unsigned u;
    memcpy(&u, &h, 4);
    return u;
}

__global__ void k_zero() {
    int i0 = blockIdx.x * blockDim.x + threadIdx.x;
    if (i0 < NN) s_deg[i0] = 0;
    if (i0 < 5 * 256) { s_sum[i0] = 0.0f; s_sq[i0] = 0.0f; }
}

__global__ void k_detect(const int* __restrict__ ei32) {
    if (threadIdx.x == 0 && blockIdx.x == 0) {
        int nz = 0;
        for (int i = 0; i < 256; i++) nz |= ei32[2 * i + 1];
        g_is64 = (nz == 0) ? 1 : 0;
    }
}

__global__ void k_decode(const void* __restrict__ ei) {
    int e = blockIdx.x * blockDim.x + threadIdx.x;
    if (e >= NE) return;
    if (g_is64) {
        const long long* p = (const long long*)ei;
        s_u[e] = (int)p[e];
        s_v[e] = (int)p[NE + e];
    } else {
        const int* p = (const int*)ei;
        s_u[e] = p[e];
        s_v[e] = p[NE + e];
    }
}

// ---- CSR build ----
__global__ void k_hist() {
    int e = blockIdx.x * blockDim.x + threadIdx.x;
    if (e >= NE) return;
    atomicAdd(&s_deg[s_u[e]], 1);
    atomicAdd(&s_deg[s_v[e]], 1);
}

__global__ void k_scan() {   // single block, 1024 threads; 20 nodes/thread
    __shared__ int ts[1024];
    int t = threadIdx.x;
    int base = t * 20;
    int lv[20];
    int loc = 0;
#pragma unroll
    for (int i = 0; i < 20; i++) {
        int n = base + i;
        lv[i] = (n < NN) ? s_deg[n] : 0;
        loc += lv[i];
    }
    ts[t] = loc;
    __syncthreads();
    for (int off = 1; off < 1024; off <<= 1) {
        int v = (t >= off) ? ts[t - off] : 0;
        __syncthreads();
        ts[t] += v;
        __syncthreads();
    }
    int run = ts[t] - loc;   // exclusive prefix
#pragma unroll
    for (int i = 0; i < 20; i++) {
        int n = base + i;
        if (n < NN) {
            s_rowptr[n] = run;
            s_cursor[n] = run;
            run += lv[i];
        }
    }
    if (t == 1023) s_rowptr[NN] = ts[1023];
}

__global__ void k_place() {
    int e = blockIdx.x * blockDim.x + threadIdx.x;
    if (e >= NE) return;
    int p0 = atomicAdd(&s_cursor[s_u[e]], 1);
    s_csr[p0] = 2 * e;
    int p1 = atomicAdd(&s_cursor[s_v[e]], 1);
    s_csr[p1] = 2 * e + 1;
}

// convert + transpose weights to fp16 n-major
__global__ void k_wprep(const float* __restrict__ w_np1, const float* __restrict__ w_np2,
                        const float* __restrict__ w_ep1, const float* __restrict__ w_ep2,
                        const float* __restrict__ w_l1) {
    int i = blockIdx.x * blockDim.x + threadIdx.x;   // 65536 threads
    if (i < 256 * 128) {            // np1: [128][256] -> [256][128]
        int n = i >> 7, k = i & 127;
        w_np1h[i] = __float2half_rn(w_np1[k * 256 + n]);
    }
    if (i < 128 * 256) {            // np2: [256][128] -> [128][256]
        int n = i >> 8, k = i & 255;
        w_np2h[i] = __float2half_rn(w_np2[k * 128 + n]);
    }
    if (i < 256 * 256) {            // ep1: [256][256] -> transposed
        int n = i >> 8, k = i & 255;
        w_ep1h[i] = __float2half_rn(w_ep1[k * 256 + n]);
    }
    if (i < 128 * 256) {            // ep2: [256][128] -> [128][256]
        int n = i >> 8, k = i & 255;
        w_ep2h[i] = __float2half_rn(w_ep2[k * 128 + n]);
    }
    if (i < 3 * 128 * 128) {        // lvl1 blocks: [384][128] -> 3x [128][128] n-major
        int blk = i >> 14, rem = i & 16383;
        int n = rem >> 7, k = rem & 127;
        w_l1h[i] = __float2half_rn(w_l1[(blk * 128 + k) * 128 + n]);
    }
}

__device__ __forceinline__ void cpasync16(void* smem_ptr, const void* gptr, int src_bytes) {
    unsigned saddr = (unsigned)__cvta_generic_to_shared(smem_ptr);
    asm volatile("cp.async.cg.shared.global [%0], [%1], 16, %2;"
                 :: "r"(saddr), "l"(gptr), "r"(src_bytes));
}
__device__ __forceinline__ void cpasync_commit() {
    asm volatile("cp.async.commit_group;");
}
template <int N>
__device__ __forceinline__ void cpasync_wait() {
    asm volatile("cp.async.wait_group %0;" :: "n"(N));
}

#define MMA_F16(d, Af, Bf)                                                      \
    asm volatile(                                                               \
        "mma.sync.aligned.m16n8k16.row.col.f32.f16.f16.f32 "                    \
        "{%0,%1,%2,%3},{%4,%5,%6,%7},{%8,%9},{%0,%1,%2,%3};"                    \
        : "+f"(d[0]), "+f"(d[1]), "+f"(d[2]), "+f"(d[3])                        \
        : "r"(Af[0]), "r"(Af[1]), "r"(Af[2]), "r"(Af[3]),                       \
          "r"(Bf[0]), "r"(Bf[1]))

// typed stores (stats on stored/rounded values)
__device__ __forceinline__ void st2(float* C, size_t off, float c0, float c1,
                                    float& r0, float& r1) {
    *(float2*)(C + off) = make_float2(c0, c1);
    r0 = c0; r1 = c1;
}
__device__ __forceinline__ void st2(__half* C, size_t off, float c0, float c1,
                                    float& r0, float& r1) {
    __half2 h = __floats2half2_rn(c0, c1);
    *(__half2*)(C + off) = h;
    r0 = __low2float(h); r1 = __high2float(h);
}

#define HSTR 40
#define HA_TILE (128 * HSTR)

// ======== HMMA GEMM, fp32 A (cvt at smem->reg), fp16 n-major B, half C ========
#define AF_STRIDE 36
#define SMEM_BYTES_FH (2 * 128 * AF_STRIDE * 4 + 2 * HA_TILE * 2 + 1024)  // 58368

__global__ __launch_bounds__(256, 2) void k_mma_fh(
    const float* __restrict__ A, const __half* __restrict__ Bt,
    __half* __restrict__ C, int M, int K, int NC)
{
    extern __shared__ char dsmRaw[];
    float* AsB = (float*)dsmRaw;
    __half* BsB = (__half*)(dsmRaw + 2 * 128 * AF_STRIDE * 4);

    const int tid = threadIdx.x;
    const int lane = tid & 31, warp = tid >> 5;
    const int group = lane >> 2, qt = lane & 3;
    const int warpM = warp & 1, warpN = warp >> 1;
    const int mBase = blockIdx.x * 128, nBase = blockIdx.y * 128;
    const int nk = K >> 5;

    const int arow = tid >> 3, akq = (tid & 7) << 2;     // fp32: 8 thr/row
    const int brow = tid >> 2, bkq = (tid & 3) << 3;     // fp16: 4 thr/row

    auto issue = [&](int i, int b) {
        const int k0 = i << 5;
        float* As = AsB + b * 128 * AF_STRIDE;
        __half* Bs = BsB + b * HA_TILE;
#pragma unroll
        for (int it = 0; it < 4; it++) {
            int row = arow + it * 32;
            int gm = mBase + row;
            const float* src = A + (size_t)(gm < M ? gm : 0) * K + k0 + akq;
            cpasync16(As + row * AF_STRIDE + akq, src, gm < M ? 16 : 0);
        }
#pragma unroll
        for (int it = 0; it < 2; it++) {
            int row = brow + it * 64;
            const __half* src = Bt + (size_t)(nBase + row) * K + k0 + bkq;
            cpasync16(Bs + row * HSTR + bkq, src, 16);
        }
        cpasync_commit();
    };

    float acc[4][4][4];
#pragma unroll
    for (int mt = 0; mt < 4; mt++)
#pragma unroll
        for (int nt = 0; nt < 4; nt++)
#pragma unroll
            for (int i = 0; i < 4; i++) acc[mt][nt][i] = 0.0f;

    issue(0, 0);
    for (int i = 0; i < nk; i++) {
        if (i + 1 < nk) { issue(i + 1, (i + 1) & 1); cpasync_wait<1>(); }
        else            { cpasync_wait<0>(); }
        __syncthreads();
        const float* As = AsB + (i & 1) * 128 * AF_STRIDE;
        const __half* Bs = BsB + (i & 1) * HA_TILE;
#pragma unroll
        for (int ks = 0; ks < 2; ks++) {
            const int kb = ks * 16 + 2 * qt;
            unsigned af[4][4], bf[4][2];
#pragma unroll
            for (int mt = 0; mt < 4; mt++) {
                int r = warpM * 64 + mt * 16 + group;
                float2 v0 = *(const float2*)(As + r * AF_STRIDE + kb);
                float2 v1 = *(const float2*)(As + (r + 8) * AF_STRIDE + kb);
                float2 v2 = *(const float2*)(As + r * AF_STRIDE + kb + 8);
                float2 v3 = *(const float2*)(As + (r + 8) * AF_STRIDE + kb + 8);
                af[mt][0] = h2u(__floats2half2_rn(v0.x, v0.y));
                af[mt][1] = h2u(__floats2half2_rn(v1.x, v1.y));
                af[mt][2] = h2u(__floats2half2_rn(v2.x, v2.y));
                af[mt][3] = h2u(__floats2half2_rn(v3.x, v3.y));
            }
#pragma unroll
            for (int nt = 0; nt < 4; nt++) {
                int cb = warpN * 32 + nt * 8 + group;
                const __half* q = Bs + cb * HSTR + kb;
                bf[nt][0] = *(const unsigned*)q;
                bf[nt][1] = *(const unsigned*)(q + 8);
            }
#pragma unroll
            for (int mt = 0; mt < 4; mt++)
#pragma unroll
                for (int nt = 0; nt < 4; nt++)
                    MMA_F16(acc[mt][nt], af[mt], bf[nt]);
        }
        __syncthreads();
    }

#pragma unroll
    for (int mt = 0; mt < 4; mt++) {
        int r0 = mBase + warpM * 64 + mt * 16 + group;
        int r1 = r0 + 8;
#pragma unroll
        for (int nt = 0; nt < 4; nt++) {
            int cc = nBase + warpN * 32 + nt * 8 + 2 * qt;
            float x0, x1;
            if (r0 < M) st2(C, (size_t)r0 * NC + cc, acc[mt][nt][0], acc[mt][nt][1], x0, x1);
            if (r1 < M) st2(C, (size_t)r1 * NC + cc, acc[mt][nt][2], acc[mt][nt][3], x0, x1);
        }
    }
}

// ======== pre1 GEMM + fused ein emit ========
// pre1 = er @ W2c + a0[u]+a0[v]+a1[atom] (stats slot0);
// epilogue also emits ein rows for this block's 64 edges (er re-read is L2-hot).
__global__ __launch_bounds__(256, 2) void k_mma_pre1(
    const float* __restrict__ A /* er */, const __half* __restrict__ Bt,
    __half* __restrict__ C, float* __restrict__ sumO, float* __restrict__ sqO,
    const float* __restrict__ nr, const float* __restrict__ eps2p)
{
    extern __shared__ char dsmRaw[];
    float* AsB = (float*)dsmRaw;
    __half* BsB = (__half*)(dsmRaw + 2 * 128 * AF_STRIDE * 4);

    const int tid = threadIdx.x;
    const int lane = tid & 31, warp = tid >> 5;
    const int group = lane >> 2, qt = lane & 3;
    const int warpM = warp & 1, warpN = warp >> 1;
    const int mBase = blockIdx.x * 128;
    const int K = 128, NC = 128, nk = 4;

    const int arow = tid >> 3, akq = (tid & 7) << 2;
    const int brow = tid >> 2, bkq = (tid & 3) << 3;

    auto issue = [&](int i, int b) {
        const int k0 = i << 5;
        float* As = AsB + b * 128 * AF_STRIDE;
        __half* Bs = BsB + b * HA_TILE;
#pragma unroll
        for (int it = 0; it < 4; it++) {
            int row = arow + it * 32;
            const float* src = A + (size_t)(mBase + row) * K + k0 + akq;
            cpasync16(As + row * AF_STRIDE + akq, src, 16);
        }
#pragma unroll
        for (int it = 0; it < 2; it++) {
            int row = brow + it * 64;
            const __half* src = Bt + (size_t)row * K + k0 + bkq;
            cpasync16(Bs + row * HSTR + bkq, src, 16);
        }
        cpasync_commit();
    };

    float acc[4][4][4];
#pragma unroll
    for (int mt = 0; mt < 4; mt++)
#pragma unroll
        for (int nt = 0; nt < 4; nt++)
#pragma unroll
            for (int i = 0; i < 4; i++) acc[mt][nt][i] = 0.0f;

    issue(0, 0);
    for (int i = 0; i < nk; i++) {
        if (i + 1 < nk) { issue(i + 1, (i + 1) & 1); cpasync_wait<1>(); }
        else            { cpasync_wait<0>(); }
        __syncthreads();
        const float* As = AsB + (i & 1) * 128 * AF_STRIDE;
        const __half* Bs = BsB + (i & 1) * HA_TILE;
#pragma unroll
        for (int ks = 0; ks < 2; ks++) {
            const int kb = ks * 16 + 2 * qt;
            unsigned af[4][4], bf[4][2];
#pragma unroll
            for (int mt = 0; mt < 4; mt++) {
                int r = warpM * 64 + mt * 16 + group;
                float2 v0 = *(const float2*)(As + r * AF_STRIDE + kb);
                float2 v1 = *(const float2*)(As + (r + 8) * AF_STRIDE + kb);
                float2 v2 = *(const float2*)(As + r * AF_STRIDE + kb + 8);
                float2 v3 = *(const float2*)(As + (r + 8) * AF_STRIDE + kb + 8);
                af[mt][0] = h2u(__floats2half2_rn(v0.x, v0.y));
                af[mt][1] = h2u(__floats2half2_rn(v1.x, v1.y));
                af[mt][2] = h2u(__floats2half2_rn(v2.x, v2.y));
                af[mt][3] = h2u(__floats2half2_rn(v3.x, v3.y));
            }
#pragma unroll
            for (int nt = 0; nt < 4; nt++) {
                int cb = warpN * 32 + nt * 8 + group;
                const __half* q = Bs + cb * HSTR + kb;
                bf[nt][0] = *(const unsigned*)q;
                bf[nt][1] = *(const unsigned*)(q + 8);
            }
#pragma unroll
            for (int mt = 0; mt < 4; mt++)
#pragma unroll
                for (int nt = 0; nt < 4; nt++)
                    MMA_F16(acc[mt][nt], af[mt], bf[nt]);
        }
        __syncthreads();
    }

    // ---- ein emit: 64 threads/edge, 4 edges/pass, 16 passes; er re-read is L2-hot ----
    {
        const float2* er2 = (const float2*)A;
        const float2* nr2 = (const float2*)nr;
        __half2* ein = (__half2*)s_ein;
        float e2 = 1.0f + *eps2p;
        float e2h = 0.5f * e2;
        int cc2 = tid & 63;
        int eo = tid >> 6;
        for (int it2 = 0; it2 < 16; it2++) {
            int e = (mBase >> 1) + it2 * 4 + eo;
            int u = s_u[e], v = s_v[e];
            float2 a = er2[(size_t)(2 * e) * 64 + cc2];
            float2 bq = er2[(size_t)(2 * e + 1) * 64 + cc2];
            float2 p = nr2[(size_t)u * 64 + cc2];
            float2 q = nr2[(size_t)v * 64 + cc2];
            __half2 fh = __floats2half2_rn(e2h * (a.x + bq.x) + p.x + q.x,
                                           e2h * (a.y + bq.y) + p.y + q.y);
            size_t r0 = (size_t)(2 * e) * 128 + cc2, r1 = (size_t)(2 * e + 1) * 128 + cc2;
            ein[r0] = fh;
            ein[r1] = fh;
            ein[r0 + 64] = __floats2half2_rn(e2 * a.x + p.x,  e2 * a.y + p.y);
            ein[r1 + 64] = __floats2half2_rn(e2 * bq.x + q.x, e2 * bq.y + q.y);
        }
    }

    // ---- pre1 epilogue: add gathered node terms (a0/a1 fp16, L2-resident), store, stats ----
    float cs[4][2], cq[4][2];
#pragma unroll
    for (int nt = 0; nt < 4; nt++) { cs[nt][0] = cs[nt][1] = 0.f; cq[nt][0] = cq[nt][1] = 0.f; }
#pragma unroll
    for (int mt = 0; mt < 4; mt++) {
        int r0 = mBase + warpM * 64 + mt * 16 + group;
        int r1 = r0 + 8;
        int e0 = r0 >> 1, e1 = r1 >> 1;
        int u0 = s_u[e0], v0 = s_v[e0];
        int u1 = s_u[e1], v1 = s_v[e1];
        const __half* b0u = s_a0 + (size_t)u0 * 128;
        const __half* b0v = s_a0 + (size_t)v0 * 128;
        const __half* b0x = s_a1 + (size_t)((r0 & 1) ? v0 : u0) * 128;
        const __half* b1u = s_a0 + (size_t)u1 * 128;
        const __half* b1v = s_a0 + (size_t)v1 * 128;
        const __half* b1x = s_a1 + (size_t)((r1 & 1) ? v1 : u1) * 128;
#pragma unroll
        for (int nt = 0; nt < 4; nt++) {
            int cc = warpN * 32 + nt * 8 + 2 * qt;
            float2 ga = __half22float2(*(const __half2*)(b0u + cc));
            float2 gb = __half22float2(*(const __half2*)(b0v + cc));
            float2 gc = __half22float2(*(const __half2*)(b0x + cc));
            float x0, x1;
            st2(C, (size_t)r0 * NC + cc,
                acc[mt][nt][0] + ga.x + gb.x + gc.x,
                acc[mt][nt][1] + ga.y + gb.y + gc.y, x0, x1);
            cs[nt][0] += x0; cs[nt][1] += x1;
            cq[nt][0] += x0 * x0; cq[nt][1] += x1 * x1;

            float2 ha = __half22float2(*(const __half2*)(b1u + cc));
            float2 hb = __half22float2(*(const __half2*)(b1v + cc));
            float2 hc = __half22float2(*(const __half2*)(b1x + cc));
            st2(C, (size_t)r1 * NC + cc,
                acc[mt][nt][2] + ha.x + hb.x + hc.x,
                acc[mt][nt][3] + ha.y + hb.y + hc.y, x0, x1);
            cs[nt][0] += x0; cs[nt][1] += x1;
            cq[nt][0] += x0 * x0; cq[nt][1] += x1 * x1;
        }
    }
#pragma unroll
    for (int off = 4; off < 32; off <<= 1) {
#pragma unroll
        for (int nt = 0; nt < 4; nt++) {
#pragma unroll
            for (int p = 0; p < 2; p++) {
                cs[nt][p] += __shfl_xor_sync(0xffffffffu, cs[nt][p], off);
                cq[nt][p] += __shfl_xor_sync(0xffffffffu, cq[nt][p], off);
            }
        }
    }
    if (group == 0) {
#pragma unroll
        for (int nt = 0; nt < 4; nt++) {
            int cc = warpN * 32 + nt * 8 + 2 * qt;
            atomicAdd(sumO + cc,     cs[nt][0]);
            atomicAdd(sumO + cc + 1, cs[nt][1]);
            atomicAdd(sqO  + cc,     cq[nt][0]);
            atomicAdd(sqO  + cc + 1, cq[nt][1]);
        }
    }
}

// ================= FP16 HMMA GEMM (half A [M][K], half B n-major [NC][K]) ==========
#define SMEM_BYTES_H (4 * HA_TILE * 2 + 2048)   // 2 A-bufs + 2 B-bufs + BN = 43008

template <typename TC, bool FUSE_BN, bool SWAP>
__global__ __launch_bounds__(256, 2) void k_mma_h(
    const __half* __restrict__ A, const __half* __restrict__ Bt,
    TC* __restrict__ C, int M, int K, int NC,
    float* __restrict__ sumO, float* __restrict__ sqO,
    const float* __restrict__ aSum, const float* __restrict__ aSq,
    const float* __restrict__ aG, const float* __restrict__ aBt, float aInv)
{
    extern __shared__ char dsmRaw[];
    __half* AsB = (__half*)dsmRaw;
    __half* BsB = (__half*)(dsmRaw + 2 * HA_TILE * 2);
    float* scS = (float*)(dsmRaw + 4 * HA_TILE * 2);
    float* shS = scS + 256;

    const int tid = threadIdx.x;
    const int lane = tid & 31, warp = tid >> 5;
    const int group = lane >> 2, qt = lane & 3;
    const int warpM = warp & 1, warpN = warp >> 1;
    const int mBase = (SWAP ? blockIdx.y : blockIdx.x) * 128;
    const int nBase = (SWAP ? blockIdx.x : blockIdx.y) * 128;
    const int nk = K >> 5;

    if (FUSE_BN) {
        if (tid < K) {
            float mean = aSum[tid] * aInv;
            float var  = aSq[tid] * aInv - mean * mean;
            float s = aG[tid] * rsqrtf(var + 1e-5f);
            scS[tid] = s; shS[tid] = aBt[tid] - mean * s;
        }
        __syncthreads();
    }

    const int arow = tid >> 2, akq = (tid & 3) << 3;  // halfs: TPR=4, RPI=64

    auto issue = [&](int i, int b) {
        const int k0 = i << 5;
        __half* As = AsB + b * HA_TILE;
        __half* Bs = BsB + b * HA_TILE;
#pragma unroll
        for (int it = 0; it < 2; it++) {
            int row = arow + it * 64;
            int gm = mBase + row;
            const __half* src = A + (size_t)(gm < M ? gm : 0) * K + k0 + akq;
            cpasync16(As + row * HSTR + akq, src, gm < M ? 16 : 0);
        }
#pragma unroll
        for (int it = 0; it < 2; it++) {
            int row = arow + it * 64;
            const __half* src = Bt + (size_t)(nBase + row) * K + k0 + akq;
            cpasync16(Bs + row * HSTR + akq, src, 16);
        }
        cpasync_commit();
    };

    float acc[4][4][4];
#pragma unroll
    for (int mt = 0; mt < 4; mt++)
#pragma unroll
        for (int nt = 0; nt < 4; nt++)
#pragma unroll
            for (int i = 0; i < 4; i++) acc[mt][nt][i] = 0.0f;

    issue(0, 0);
    for (int i = 0; i < nk; i++) {
        if (i + 1 < nk) { issue(i + 1, (i + 1) & 1); cpasync_wait<1>(); }
        else            { cpasync_wait<0>(); }
        __syncthreads();
        const __half* As = AsB + (i & 1) * HA_TILE;
        const __half* Bs = BsB + (i & 1) * HA_TILE;
        const int k0 = i << 5;
#pragma unroll
        for (int ks = 0; ks < 2; ks++) {
            const int kb = ks * 16 + 2 * qt;
            unsigned af[4][4], bf[4][2];
            float sc0, sh0, sc1, sh1, sc8, sh8, sc9, sh9;
            if (FUSE_BN) {
                int g = k0 + kb;
                sc0 = scS[g];     sh0 = shS[g];
                sc1 = scS[g + 1]; sh1 = shS[g + 1];
                sc8 = scS[g + 8]; sh8 = shS[g + 8];
                sc9 = scS[g + 9]; sh9 = shS[g + 9];
            }
#pragma unroll
            for (int mt = 0; mt < 4; mt++) {
                int r = warpM * 64 + mt * 16 + group;
                const __half* p0 = As + r * HSTR + kb;
                const __half* p1 = As + (r + 8) * HSTR + kb;
                if (FUSE_BN) {
                    float2 v0 = __half22float2(*(const __half2*)p0);
                    float2 v1 = __half22float2(*(const __half2*)p1);
                    float2 v2 = __half22float2(*(const __half2*)(p0 + 8));
                    float2 v3 = __half22float2(*(const __half2*)(p1 + 8));
                    af[mt][0] = h2u(__floats2half2_rn(
                        fmaxf(fmaf(v0.x, sc0, sh0), 0.f), fmaxf(fmaf(v0.y, sc1, sh1), 0.f)));
                    af[mt][1] = h2u(__floats2half2_rn(
                        fmaxf(fmaf(v1.x, sc0, sh0), 0.f), fmaxf(fmaf(v1.y, sc1, sh1), 0.f)));
                    af[mt][2] = h2u(__floats2half2_rn(
                        fmaxf(fmaf(v2.x, sc8, sh8), 0.f), fmaxf(fmaf(v2.y, sc9, sh9), 0.f)));
                    af[mt][3] = h2u(__floats2half2_rn(
                        fmaxf(fmaf(v3.x, sc8, sh8), 0.f), fmaxf(fmaf(v3.y, sc9, sh9), 0.f)));
                } else {
                    af[mt][0] = *(const unsigned*)p0;
                    af[mt][1] = *(const unsigned*)p1;
                    af[mt][2] = *(const unsigned*)(p0 + 8);
                    af[mt][3] = *(const unsigned*)(p1 + 8);
                }
            }
#pragma unroll
            for (int nt = 0; nt < 4; nt++) {
                int cb = warpN * 32 + nt * 8 + group;
                const __half* q = Bs + cb * HSTR + kb;
                bf[nt][0] = *(const unsigned*)q;
                bf[nt][1] = *(const unsigned*)(q + 8);
            }
#pragma unroll
            for (int mt = 0; mt < 4; mt++)
#pragma unroll
                for (int nt = 0; nt < 4; nt++)
                    MMA_F16(acc[mt][nt], af[mt], bf[nt]);
        }
        __syncthreads();
    }

    // epilogue: store + BN stats (on stored values)
    float cs[4][2], cq[4][2];
#pragma unroll
    for (int nt = 0; nt < 4; nt++) { cs[nt][0] = cs[nt][1] = 0.f; cq[nt][0] = cq[nt][1] = 0.f; }
#pragma unroll
    for (int mt = 0; mt < 4; mt++) {
        int r0 = mBase + warpM * 64 + mt * 16 + group;
        int r1 = r0 + 8;
#pragma unroll
        for (int nt = 0; nt < 4; nt++) {
            int cc = nBase + warpN * 32 + nt * 8 + 2 * qt;
            float x0, x1;
            if (r0 < M) {
                st2(C, (size_t)r0 * NC + cc, acc[mt][nt][0], acc[mt][nt][1], x0, x1);
                cs[nt][0] += x0; cs[nt][1] += x1;
                cq[nt][0] += x0 * x0; cq[nt][1] += x1 * x1;
            }
            if (r1 < M) {
                st2(C, (size_t)r1 * NC + cc, acc[mt][nt][2], acc[mt][nt][3], x0, x1);
                cs[nt][0] += x0; cs[nt][1] += x1;
                cq[nt][0] += x0 * x0; cq[nt][1] += x1 * x1;
            }
        }
    }
    if (sumO) {
#pragma unroll
        for (int off = 4; off < 32; off <<= 1) {
#pragma unroll
            for (int nt = 0; nt < 4; nt++) {
#pragma unroll
                for (int p = 0; p < 2; p++) {
                    cs[nt][p] += __shfl_xor_sync(0xffffffffu, cs[nt][p], off);
                    cq[nt][p] += __shfl_xor_sync(0xffffffffu, cq[nt][p], off);
                }
            }
        }
        if (group == 0) {
#pragma unroll
            for (int nt = 0; nt < 4; nt++) {
                int cc = nBase + warpN * 32 + nt * 8 + 2 * qt;
                atomicAdd(sumO + cc,     cs[nt][0]);
                atomicAdd(sumO + cc + 1, cs[nt][1]);
                atomicAdd(sqO  + cc,     cq[nt][0]);
                atomicAdd(sqO  + cc + 1, cq[nt][1]);
            }
        }
    }
}

// CSR gather: nin[n] = e11*nr[n] + sum_entries[(2+eps12)*h_r + h_sib]
__global__ void k_gather_nin(const float* __restrict__ nr,
                             const float* __restrict__ g, const float* __restrict__ b,
                             const float* __restrict__ eps12p,
                             const float* __restrict__ eps11p) {
    int n = blockIdx.x;
    int c = threadIdx.x;
    float mean = s_sum[c] * (1.0f / TE);
    float var  = s_sq[c]  * (1.0f / TE) - mean * mean;
    float sc = g[c] * rsqrtf(var + 1e-5f);
    float sh = b[c] - mean * sc;
    float cf = 2.0f + *eps12p;
    float e11 = 1.0f + *eps11p;
    int beg = s_rowptr[n], end = s_rowptr[n + 1];
    float acc = 0.f;
    for (int j = beg; j < end; j++) {
        int r = s_csr[j];
        int sIb = r ^ 1;
        float hr = fmaxf(__half2float(s_pre1[(size_t)r  * 128 + c]) * sc + sh, 0.f);
        float hs = fmaxf(__half2float(s_pre1[(size_t)sIb * 128 + c]) * sc + sh, 0.f);
        acc += cf * hr + hs;
    }
    s_nin[(size_t)n * 128 + c] = __float2half_rn(e11 * nr[(size_t)n * 128 + c] + acc);
}

// dst(fp32) = relu(src(half)*scale + shift); half2 vectorized; cols = 128 (64 half2)
__global__ void k_bnapplyh(const __half2* __restrict__ src, float2* __restrict__ dst,
                           int rows,
                           const float* __restrict__ sum, const float* __restrict__ sq,
                           const float* __restrict__ g, const float* __restrict__ b,
                           float inv) {
    size_t n = (size_t)rows * 64;
    size_t stride = (size_t)gridDim.x * blockDim.x;
    for (size_t i = (size_t)blockIdx.x * blockDim.x + threadIdx.x; i < n; i += stride) {
        int c = (int)(i & 63) << 1;
        float2 v = __half22float2(src[i]);
        float m0 = sum[c] * inv, m1 = sum[c + 1] * inv;
        float v0 = sq[c] * inv - m0 * m0, v1 = sq[c + 1] * inv - m1 * m1;
        float s0 = g[c] * rsqrtf(v0 + 1e-5f), s1 = g[c + 1] * rsqrtf(v1 + 1e-5f);
        float o0 = fmaxf(v.x * s0 + (b[c] - m0 * s0), 0.f);
        float o1 = fmaxf(v.y * s1 + (b[c + 1] - m1 * s1), 0.f);
        dst[i] = make_float2(o0, o1);
    }
}

// ---------------- launch ----------------
extern "C" void kernel_launch(void* const* d_in, const int* in_sizes, int n_in,
                              void* d_out, int out_size) {
    const float* nr      = (const float*)d_in[0];
    const float* er      = (const float*)d_in[1];
    const void*  ei      = d_in[2];
    const float* lift_w1 = (const float*)d_in[3];
    const float* lift_g1 = (const float*)d_in[4];
    const float* lift_b1 = (const float*)d_in[5];
    const float* lift_w2 = (const float*)d_in[6];
    const float* lift_g2 = (const float*)d_in[7];
    const float* lift_b2 = (const float*)d_in[8];
    const float* lvl1_w  = (const float*)d_in[9];
    const float* lvl1_g  = (const float*)d_in[10];
    const float* lvl1_b  = (const float*)d_in[11];
    const float* lvl2_w1 = (const float*)d_in[12];
    const float* lvl2_g1 = (const float*)d_in[13];
    const float* lvl2_b1 = (const float*)d_in[14];
    const float* lvl2_w2 = (const float*)d_in[15];
    const float* lvl2_g2 = (const float*)d_in[16];
    const float* lvl2_b2 = (const float*)d_in[17];
    const float* eps11   = (const float*)d_in[18];
    const float* eps12   = (const float*)d_in[19];
    const float* eps2    = (const float*)d_in[20];

    float* out_node = (float*)d_out;
    float* out_edge = out_node + (size_t)NN * HH;

    __half *p_a0, *p_a1, *p_nin, *p_np1, *p_np2, *p_ein, *p_ep1, *p_ep2, *p_pre1;
    __half *p_wnp1, *p_wnp2, *p_wep1, *p_wep2, *p_wl1;
    float *p_sum, *p_sq;
    cudaGetSymbolAddress((void**)&p_a0,  s_a0);
    cudaGetSymbolAddress((void**)&p_a1,  s_a1);
    cudaGetSymbolAddress((void**)&p_pre1, s_pre1);
    cudaGetSymbolAddress((void**)&p_nin, s_nin);
    cudaGetSymbolAddress((void**)&p_np1, s_np1);
    cudaGetSymbolAddress((void**)&p_np2, s_np2);
    cudaGetSymbolAddress((void**)&p_ein, s_ein);
    cudaGetSymbolAddress((void**)&p_ep1, s_ep1);
    cudaGetSymbolAddress((void**)&p_ep2, s_ep2);
    cudaGetSymbolAddress((void**)&p_sum, s_sum);
    cudaGetSymbolAddress((void**)&p_sq,  s_sq);
    cudaGetSymbolAddress((void**)&p_wnp1, w_np1h);
    cudaGetSymbolAddress((void**)&p_wnp2, w_np2h);
    cudaGetSymbolAddress((void**)&p_wep1, w_ep1h);
    cudaGetSymbolAddress((void**)&p_wep2, w_ep2h);
    cudaGetSymbolAddress((void**)&p_wl1,  w_l1h);

    static cudaStream_t s_edge = nullptr, s_csrS = nullptr;
    static cudaEvent_t ev_root = nullptr, ev_dec = nullptr, ev_a01 = nullptr,
                       ev_pre1 = nullptr, ev_edge = nullptr, ev_csr = nullptr;
    static int smem_set = 0;
    if (!smem_set) {
        cudaFuncSetAttribute((const void*)k_mma_fh,
                             cudaFuncAttributeMaxDynamicSharedMemorySize, SMEM_BYTES_FH);
        cudaFuncSetAttribute((const void*)k_mma_pre1,
                             cudaFuncAttributeMaxDynamicSharedMemorySize, SMEM_BYTES_FH);
        cudaFuncSetAttribute((const void*)k_mma_h<__half, false, true>,
                             cudaFuncAttributeMaxDynamicSharedMemorySize, SMEM_BYTES_H);
        cudaFuncSetAttribute((const void*)k_mma_h<__half, true, false>,
                             cudaFuncAttributeMaxDynamicSharedMemorySize, SMEM_BYTES_H);
        cudaStreamCreateWithFlags(&s_edge, cudaStreamNonBlocking);
        cudaStreamCreateWithFlags(&s_csrS, cudaStreamNonBlocking);
        cudaEventCreateWithFlags(&ev_root, cudaEventDisableTiming);
        cudaEventCreateWithFlags(&ev_dec,  cudaEventDisableTiming);
        cudaEventCreateWithFlags(&ev_a01,  cudaEventDisableTiming);
        cudaEventCreateWithFlags(&ev_pre1, cudaEventDisableTiming);
        cudaEventCreateWithFlags(&ev_edge, cudaEventDisableTiming);
        cudaEventCreateWithFlags(&ev_csr,  cudaEventDisableTiming);
        smem_set = 1;
    }

    const int GN  = (NN + 127) / 128;  // 157
    const int GTE = TE / 128;          // 2500

    // -------- root fork: side streams join capture via event-wait --------
    cudaEventRecord(ev_root, 0);
    cudaStreamWaitEvent(s_csrS, ev_root, 0);

    // stream 0: index decode        s_csrS: zero + wprep + a0/a1 GEMMs (parallel)
    k_detect<<<1, 32>>>((const int*)ei);
    k_decode<<<(NE + 255) / 256, 256>>>(ei);
    cudaEventRecord(ev_dec, 0);

    k_zero<<<(NN + 255) / 256, 256, 0, s_csrS>>>();
    k_wprep<<<256, 256, 0, s_csrS>>>(lvl2_w1, lvl2_w2, lift_w1, lift_w2, lvl1_w);
    k_mma_fh<<<dim3(GN, 1), 256, SMEM_BYTES_FH, s_csrS>>>(nr, p_wl1,         p_a0, NN, 128, 128);
    k_mma_fh<<<dim3(GN, 1), 256, SMEM_BYTES_FH, s_csrS>>>(nr, p_wl1 + 16384, p_a1, NN, 128, 128);
    cudaEventRecord(ev_a01, s_csrS);

    // CSR build on s_csrS (needs decode)
    cudaStreamWaitEvent(s_csrS, ev_dec, 0);
    k_hist<<<(NE + 255) / 256, 256, 0, s_csrS>>>();
    k_scan<<<1, 1024, 0, s_csrS>>>();
    k_place<<<(NE + 255) / 256, 256, 0, s_csrS>>>();
    cudaEventRecord(ev_csr, s_csrS);

    // -------- stream 0: pre1 GEMM + fused ein emit (needs dec implicit + a0/a1 + W) ------
    cudaStreamWaitEvent(0, ev_a01, 0);
    k_mma_pre1<<<dim3(GTE, 1), 256, SMEM_BYTES_FH>>>(er, p_wl1 + 2 * 16384, p_pre1,
                                                     p_sum, p_sq, nr, eps2);
    cudaEventRecord(ev_pre1, 0);

    // -------- edge chain (s_edge): ein now produced by pre1 --------
    cudaStreamWaitEvent(s_edge, ev_pre1, 0);
    k_mma_h<__half, false, true><<<dim3(2, GTE), 256, SMEM_BYTES_H, s_edge>>>(
        p_ein, p_wep1, p_ep1, TE, 256, 256,
        p_sum + 768, p_sq + 768, nullptr, nullptr, nullptr, nullptr, 0.f);
    k_mma_h<__half, true, false><<<dim3(GTE, 1), 256, SMEM_BYTES_H, s_edge>>>(
        p_ep1, p_wep2, p_ep2, TE, 256, 128,
        p_sum + 1024, p_sq + 1024,
        p_sum + 768, p_sq + 768, lift_g1, lift_b1, 1.0f / TE);
    k_bnapplyh<<<4096, 256, 0, s_edge>>>((const __half2*)p_ep2, (float2*)out_edge, TE,
                              p_sum + 1024, p_sq + 1024, lift_g2, lift_b2, 1.0f / TE);
    cudaEventRecord(ev_edge, s_edge);

    // -------- node chain (stream 0) --------
    cudaStreamWaitEvent(0, ev_csr, 0);
    k_gather_nin<<<NN, 128>>>(nr, lvl1_g, lvl1_b, eps12, eps11);  // BN+aggregate+nin fused

    k_mma_h<__half, false, true><<<dim3(2, GN), 256, SMEM_BYTES_H>>>(
        p_nin, p_wnp1, p_np1, NN, 128, 256,
        p_sum + 256, p_sq + 256, nullptr, nullptr, nullptr, nullptr, 0.f);
    k_mma_h<__half, true, false><<<dim3(GN, 1), 256, SMEM_BYTES_H>>>(
        p_np1, p_wnp2, p_np2, NN, 256, 128,
        p_sum + 512, p_sq + 512,
        p_sum + 256, p_sq + 256, lvl2_g1, lvl2_b1, 1.0f / NN);
    k_bnapplyh<<<2048, 256>>>((const __half2*)p_np2, (float2*)out_node, NN,
                              p_sum + 512, p_sq + 512, lvl2_g2, lvl2_b2, 1.0f / NN);

    // -------- join --------
    cudaStreamWaitEvent(0, ev_edge, 0);
}

// round 17
// speedup vs baseline: 1.0617x; 1.0617x over previous
#include <cuda_runtime.h>
#include <cuda_fp16.h>
#include <cstring>

#define NN 20000      // nodes
#define NE 160000     // edges
#define TE 320000     // 2E edge-rows
#define HH 128

// ---------------- scratch (static __device__, no allocs) ----------------
__device__ __align__(128) __half s_a0  [(size_t)NN * 128];   // nr @ W0
__device__ __align__(128) __half s_a1  [(size_t)NN * 128];   // nr @ W1
__device__ __align__(128) __half s_pre1[(size_t)TE * 128];   // lvl1 pre-act
__device__ __align__(128) __half s_nin [(size_t)NN * 128];
__device__ __align__(128) __half s_np1 [(size_t)NN * 256];
__device__ __align__(128) __half s_np2 [(size_t)NN * 128];   // final pre-act (half)
__device__ __align__(128) __half s_ein [(size_t)TE * 256];
__device__ __align__(128) __half s_ep1 [(size_t)TE * 256];
__device__ __align__(128) __half s_ep2 [(size_t)TE * 128];   // final pre-act (half)
// fp16 weights, pre-transposed to n-major [N][K]
__device__ __align__(128) __half w_np1h[256 * 128];
__device__ __align__(128) __half w_np2h[128 * 256];
__device__ __align__(128) __half w_ep1h[256 * 256];
__device__ __align__(128) __half w_ep2h[128 * 256];
__device__ __align__(128) __half w_l1h [3 * 128 * 128];   // lvl1 W blocks 0,1,2 n-major
// CSR: node -> incident edge-rows
__device__ int s_deg[NN];
__device__ int s_rowptr[NN + 1];
__device__ int s_cursor[NN];
__device__ int s_csr[TE];
__device__ float s_sum[5 * 256];
__device__ float s_sq [5 * 256];
__device__ int   s_u[NE];
__device__ int   s_v[NE];
__device__ int   g_is64;

// ---------------- helpers ----------------
__device__ __forceinline__ unsigned h2u(__half2 h) {
    unsigned u;
    memcpy(&u, &h, 4);
    return u;
}

__global__ void k_zero() {
    int i0 = blockIdx.x * blockDim.x + threadIdx.x;
    if (i0 < NN) s_deg[i0] = 0;
    if (i0 < 5 * 256) { s_sum[i0] = 0.0f; s_sq[i0] = 0.0f; }
}

__global__ void k_detect(const int* __restrict__ ei32) {
    if (threadIdx.x == 0 && blockIdx.x == 0) {
        int nz = 0;
        for (int i = 0; i < 256; i++) nz |= ei32[2 * i + 1];
        g_is64 = (nz == 0) ? 1 : 0;
    }
}

__global__ void k_decode(const void* __restrict__ ei) {
    int e = blockIdx.x * blockDim.x + threadIdx.x;
    if (e >= NE) return;
    if (g_is64) {
        const long long* p = (const long long*)ei;
        s_u[e] = (int)p[e];
        s_v[e] = (int)p[NE + e];
    } else {
        const int* p = (const int*)ei;
        s_u[e] = p[e];
        s_v[e] = p[NE + e];
    }
}

// ---- CSR build ----
__global__ void k_hist() {
    int e = blockIdx.x * blockDim.x + threadIdx.x;
    if (e >= NE) return;
    atomicAdd(&s_deg[s_u[e]], 1);
    atomicAdd(&s_deg[s_v[e]], 1);
}

__global__ void k_scan() {   // single block, 1024 threads; 20 nodes/thread
    __shared__ int ts[1024];
    int t = threadIdx.x;
    int base = t * 20;
    int lv[20];
    int loc = 0;
#pragma unroll
    for (int i = 0; i < 20; i++) {
        int n = base + i;
        lv[i] = (n < NN) ? s_deg[n] : 0;
        loc += lv[i];
    }
    ts[t] = loc;
    __syncthreads();
    for (int off = 1; off < 1024; off <<= 1) {
        int v = (t >= off) ? ts[t - off] : 0;
        __syncthreads();
        ts[t] += v;
        __syncthreads();
    }
    int run = ts[t] - loc;   // exclusive prefix
#pragma unroll
    for (int i = 0; i < 20; i++) {
        int n = base + i;
        if (n < NN) {
            s_rowptr[n] = run;
            s_cursor[n] = run;
            run += lv[i];
        }
    }
    if (t == 1023) s_rowptr[NN] = ts[1023];
}

__global__ void k_place() {
    int e = blockIdx.x * blockDim.x + threadIdx.x;
    if (e >= NE) return;
    int p0 = atomicAdd(&s_cursor[s_u[e]], 1);
    s_csr[p0] = 2 * e;
    int p1 = atomicAdd(&s_cursor[s_v[e]], 1);
    s_csr[p1] = 2 * e + 1;
}

// convert + transpose weights to fp16 n-major
__global__ void k_wprep(const float* __restrict__ w_np1, const float* __restrict__ w_np2,
                        const float* __restrict__ w_ep1, const float* __restrict__ w_ep2,
                        const float* __restrict__ w_l1) {
    int i = blockIdx.x * blockDim.x + threadIdx.x;   // 65536 threads
    if (i < 256 * 128) {            // np1: [128][256] -> [256][128]
        int n = i >> 7, k = i & 127;
        w_np1h[i] = __float2half_rn(w_np1[k * 256 + n]);
    }
    if (i < 128 * 256) {            // np2: [256][128] -> [128][256]
        int n = i >> 8, k = i & 255;
        w_np2h[i] = __float2half_rn(w_np2[k * 128 + n]);
    }
    if (i < 256 * 256) {            // ep1: [256][256] -> transposed
        int n = i >> 8, k = i & 255;
        w_ep1h[i] = __float2half_rn(w_ep1[k * 256 + n]);
    }
    if (i < 128 * 256) {            // ep2: [256][128] -> [128][256]
        int n = i >> 8, k = i & 255;
        w_ep2h[i] = __float2half_rn(w_ep2[k * 128 + n]);
    }
    if (i < 3 * 128 * 128) {        // lvl1 blocks: [384][128] -> 3x [128][128] n-major
        int blk = i >> 14, rem = i & 16383;
        int n = rem >> 7, k = rem & 127;
        w_l1h[i] = __float2half_rn(w_l1[(blk * 128 + k) * 128 + n]);
    }
}

__device__ __forceinline__ void cpasync16(void* smem_ptr, const void* gptr, int src_bytes) {
    unsigned saddr = (unsigned)__cvta_generic_to_shared(smem_ptr);
    asm volatile("cp.async.cg.shared.global [%0], [%1], 16, %2;"
                 :: "r"(saddr), "l"(gptr), "r"(src_bytes));
}
__device__ __forceinline__ void cpasync_commit() {
    asm volatile("cp.async.commit_group;");
}
template <int N>
__device__ __forceinline__ void cpasync_wait() {
    asm volatile("cp.async.wait_group %0;" :: "n"(N));
}

#define MMA_F16(d, Af, Bf)                                                      \
    asm volatile(                                                               \
        "mma.sync.aligned.m16n8k16.row.col.f32.f16.f16.f32 "                    \
        "{%0,%1,%2,%3},{%4,%5,%6,%7},{%8,%9},{%0,%1,%2,%3};"                    \
        : "+f"(d[0]), "+f"(d[1]), "+f"(d[2]), "+f"(d[3])                        \
        : "r"(Af[0]), "r"(Af[1]), "r"(Af[2]), "r"(Af[3]),                       \
          "r"(Bf[0]), "r"(Bf[1]))

// typed stores (stats on stored/rounded values)
__device__ __forceinline__ void st2(float* C, size_t off, float c0, float c1,
                                    float& r0, float& r1) {
    *(float2*)(C + off) = make_float2(c0, c1);
    r0 = c0; r1 = c1;
}
__device__ __forceinline__ void st2(__half* C, size_t off, float c0, float c1,
                                    float& r0, float& r1) {
    __half2 h = __floats2half2_rn(c0, c1);
    *(__half2*)(C + off) = h;
    r0 = __low2float(h); r1 = __high2float(h);
}

#define HSTR 40
#define HA_TILE (128 * HSTR)

// ======== HMMA GEMM, fp32 A (cvt at smem->reg), fp16 n-major B, half C ========
#define AF_STRIDE 36
#define SMEM_BYTES_FH (2 * 128 * AF_STRIDE * 4 + 2 * HA_TILE * 2 + 1024)  // 58368

__global__ __launch_bounds__(256, 2) void k_mma_fh(
    const float* __restrict__ A, const __half* __restrict__ Bt,
    __half* __restrict__ C, int M, int K, int NC)
{
    extern __shared__ char dsmRaw[];
    float* AsB = (float*)dsmRaw;
    __half* BsB = (__half*)(dsmRaw + 2 * 128 * AF_STRIDE * 4);

    const int tid = threadIdx.x;
    const int lane = tid & 31, warp = tid >> 5;
    const int group = lane >> 2, qt = lane & 3;
    const int warpM = warp & 1, warpN = warp >> 1;
    const int mBase = blockIdx.x * 128, nBase = blockIdx.y * 128;
    const int nk = K >> 5;

    const int arow = tid >> 3, akq = (tid & 7) << 2;     // fp32: 8 thr/row
    const int brow = tid >> 2, bkq = (tid & 3) << 3;     // fp16: 4 thr/row

    auto issue = [&](int i, int b) {
        const int k0 = i << 5;
        float* As = AsB + b * 128 * AF_STRIDE;
        __half* Bs = BsB + b * HA_TILE;
#pragma unroll
        for (int it = 0; it < 4; it++) {
            int row = arow + it * 32;
            int gm = mBase + row;
            const float* src = A + (size_t)(gm < M ? gm : 0) * K + k0 + akq;
            cpasync16(As + row * AF_STRIDE + akq, src, gm < M ? 16 : 0);
        }
#pragma unroll
        for (int it = 0; it < 2; it++) {
            int row = brow + it * 64;
            const __half* src = Bt + (size_t)(nBase + row) * K + k0 + bkq;
            cpasync16(Bs + row * HSTR + bkq, src, 16);
        }
        cpasync_commit();
    };

    float acc[4][4][4];
#pragma unroll
    for (int mt = 0; mt < 4; mt++)
#pragma unroll
        for (int nt = 0; nt < 4; nt++)
#pragma unroll
            for (int i = 0; i < 4; i++) acc[mt][nt][i] = 0.0f;

    issue(0, 0);
    for (int i = 0; i < nk; i++) {
        if (i + 1 < nk) { issue(i + 1, (i + 1) & 1); cpasync_wait<1>(); }
        else            { cpasync_wait<0>(); }
        __syncthreads();
        const float* As = AsB + (i & 1) * 128 * AF_STRIDE;
        const __half* Bs = BsB + (i & 1) * HA_TILE;
#pragma unroll
        for (int ks = 0; ks < 2; ks++) {
            const int kb = ks * 16 + 2 * qt;
            unsigned af[4][4], bf[4][2];
#pragma unroll
            for (int mt = 0; mt < 4; mt++) {
                int r = warpM * 64 + mt * 16 + group;
                float2 v0 = *(const float2*)(As + r * AF_STRIDE + kb);
                float2 v1 = *(const float2*)(As + (r + 8) * AF_STRIDE + kb);
                float2 v2 = *(const float2*)(As + r * AF_STRIDE + kb + 8);
                float2 v3 = *(const float2*)(As + (r + 8) * AF_STRIDE + kb + 8);
                af[mt][0] = h2u(__floats2half2_rn(v0.x, v0.y));
                af[mt][1] = h2u(__floats2half2_rn(v1.x, v1.y));
                af[mt][2] = h2u(__floats2half2_rn(v2.x, v2.y));
                af[mt][3] = h2u(__floats2half2_rn(v3.x, v3.y));
            }
#pragma unroll
            for (int nt = 0; nt < 4; nt++) {
                int cb = warpN * 32 + nt * 8 + group;
                const __half* q = Bs + cb * HSTR + kb;
                bf[nt][0] = *(const unsigned*)q;
                bf[nt][1] = *(const unsigned*)(q + 8);
            }
#pragma unroll
            for (int mt = 0; mt < 4; mt++)
#pragma unroll
                for (int nt = 0; nt < 4; nt++)
                    MMA_F16(acc[mt][nt], af[mt], bf[nt]);
        }
        __syncthreads();
    }

#pragma unroll
    for (int mt = 0; mt < 4; mt++) {
        int r0 = mBase + warpM * 64 + mt * 16 + group;
        int r1 = r0 + 8;
#pragma unroll
        for (int nt = 0; nt < 4; nt++) {
            int cc = nBase + warpN * 32 + nt * 8 + 2 * qt;
            float x0, x1;
            if (r0 < M) st2(C, (size_t)r0 * NC + cc, acc[mt][nt][0], acc[mt][nt][1], x0, x1);
            if (r1 < M) st2(C, (size_t)r1 * NC + cc, acc[mt][nt][2], acc[mt][nt][3], x0, x1);
        }
    }
}

// ======== pre1 GEMM: er @ W2c, epilogue adds a0[u]+a0[v]+a1[atom], writes pre1 + stats slot0 ========
__global__ __launch_bounds__(256, 2) void k_mma_pre1(
    const float* __restrict__ A, const __half* __restrict__ Bt,
    __half* __restrict__ C, float* __restrict__ sumO, float* __restrict__ sqO)
{
    extern __shared__ char dsmRaw[];
    float* AsB = (float*)dsmRaw;
    __half* BsB = (__half*)(dsmRaw + 2 * 128 * AF_STRIDE * 4);

    const int tid = threadIdx.x;
    const int lane = tid & 31, warp = tid >> 5;
    const int group = lane >> 2, qt = lane & 3;
    const int warpM = warp & 1, warpN = warp >> 1;
    const int mBase = blockIdx.x * 128;
    const int K = 128, NC = 128, nk = 4;

    const int arow = tid >> 3, akq = (tid & 7) << 2;
    const int brow = tid >> 2, bkq = (tid & 3) << 3;

    auto issue = [&](int i, int b) {
        const int k0 = i << 5;
        float* As = AsB + b * 128 * AF_STRIDE;
        __half* Bs = BsB + b * HA_TILE;
#pragma unroll
        for (int it = 0; it < 4; it++) {
            int row = arow + it * 32;
            const float* src = A + (size_t)(mBase + row) * K + k0 + akq;
            cpasync16(As + row * AF_STRIDE + akq, src, 16);
        }
#pragma unroll
        for (int it = 0; it < 2; it++) {
            int row = brow + it * 64;
            const __half* src = Bt + (size_t)row * K + k0 + bkq;
            cpasync16(Bs + row * HSTR + bkq, src, 16);
        }
        cpasync_commit();
    };

    float acc[4][4][4];
#pragma unroll
    for (int mt = 0; mt < 4; mt++)
#pragma unroll
        for (int nt = 0; nt < 4; nt++)
#pragma unroll
            for (int i = 0; i < 4; i++) acc[mt][nt][i] = 0.0f;

    issue(0, 0);
    for (int i = 0; i < nk; i++) {
        if (i + 1 < nk) { issue(i + 1, (i + 1) & 1); cpasync_wait<1>(); }
        else            { cpasync_wait<0>(); }
        __syncthreads();
        const float* As = AsB + (i & 1) * 128 * AF_STRIDE;
        const __half* Bs = BsB + (i & 1) * HA_TILE;
#pragma unroll
        for (int ks = 0; ks < 2; ks++) {
            const int kb = ks * 16 + 2 * qt;
            unsigned af[4][4], bf[4][2];
#pragma unroll
            for (int mt = 0; mt < 4; mt++) {
                int r = warpM * 64 + mt * 16 + group;
                float2 v0 = *(const float2*)(As + r * AF_STRIDE + kb);
                float2 v1 = *(const float2*)(As + (r + 8) * AF_STRIDE + kb);
                float2 v2 = *(const float2*)(As + r * AF_STRIDE + kb + 8);
                float2 v3 = *(const float2*)(As + (r + 8) * AF_STRIDE + kb + 8);
                af[mt][0] = h2u(__floats2half2_rn(v0.x, v0.y));
                af[mt][1] = h2u(__floats2half2_rn(v1.x, v1.y));
                af[mt][2] = h2u(__floats2half2_rn(v2.x, v2.y));
                af[mt][3] = h2u(__floats2half2_rn(v3.x, v3.y));
            }
#pragma unroll
            for (int nt = 0; nt < 4; nt++) {
                int cb = warpN * 32 + nt * 8 + group;
                const __half* q = Bs + cb * HSTR + kb;
                bf[nt][0] = *(const unsigned*)q;
                bf[nt][1] = *(const unsigned*)(q + 8);
            }
#pragma unroll
            for (int mt = 0; mt < 4; mt++)
#pragma unroll
                for (int nt = 0; nt < 4; nt++)
                    MMA_F16(acc[mt][nt], af[mt], bf[nt]);
        }
        __syncthreads();
    }

    // epilogue: add gathered node terms (a0/a1 fp16, L2-resident), store half, stats
    float cs[4][2], cq[4][2];
#pragma unroll
    for (int nt = 0; nt < 4; nt++) { cs[nt][0] = cs[nt][1] = 0.f; cq[nt][0] = cq[nt][1] = 0.f; }
#pragma unroll
    for (int mt = 0; mt < 4; mt++) {
        int r0 = mBase + warpM * 64 + mt * 16 + group;
        int r1 = r0 + 8;
        int e0 = r0 >> 1, e1 = r1 >> 1;
        int u0 = s_u[e0], v0 = s_v[e0];
        int u1 = s_u[e1], v1 = s_v[e1];
        const __half* b0u = s_a0 + (size_t)u0 * 128;
        const __half* b0v = s_a0 + (size_t)v0 * 128;
        const __half* b0x = s_a1 + (size_t)((r0 & 1) ? v0 : u0) * 128;
        const __half* b1u = s_a0 + (size_t)u1 * 128;
        const __half* b1v = s_a0 + (size_t)v1 * 128;
        const __half* b1x = s_a1 + (size_t)((r1 & 1) ? v1 : u1) * 128;
#pragma unroll
        for (int nt = 0; nt < 4; nt++) {
            int cc = warpN * 32 + nt * 8 + 2 * qt;
            float2 ga = __half22float2(*(const __half2*)(b0u + cc));
            float2 gb = __half22float2(*(const __half2*)(b0v + cc));
            float2 gc = __half22float2(*(const __half2*)(b0x + cc));
            float x0, x1;
            st2(C, (size_t)r0 * NC + cc,
                acc[mt][nt][0] + ga.x + gb.x + gc.x,
                acc[mt][nt][1] + ga.y + gb.y + gc.y, x0, x1);
            cs[nt][0] += x0; cs[nt][1] += x1;
            cq[nt][0] += x0 * x0; cq[nt][1] += x1 * x1;

            float2 ha = __half22float2(*(const __half2*)(b1u + cc));
            float2 hb = __half22float2(*(const __half2*)(b1v + cc));
            float2 hc = __half22float2(*(const __half2*)(b1x + cc));
            st2(C, (size_t)r1 * NC + cc,
                acc[mt][nt][2] + ha.x + hb.x + hc.x,
                acc[mt][nt][3] + ha.y + hb.y + hc.y, x0, x1);
            cs[nt][0] += x0; cs[nt][1] += x1;
            cq[nt][0] += x0 * x0; cq[nt][1] += x1 * x1;
        }
    }
#pragma unroll
    for (int off = 4; off < 32; off <<= 1) {
#pragma unroll
        for (int nt = 0; nt < 4; nt++) {
#pragma unroll
            for (int p = 0; p < 2; p++) {
                cs[nt][p] += __shfl_xor_sync(0xffffffffu, cs[nt][p], off);
                cq[nt][p] += __shfl_xor_sync(0xffffffffu, cq[nt][p], off);
            }
        }
    }
    if (group == 0) {
#pragma unroll
        for (int nt = 0; nt < 4; nt++) {
            int cc = warpN * 32 + nt * 8 + 2 * qt;
            atomicAdd(sumO + cc,     cs[nt][0]);
            atomicAdd(sumO + cc + 1, cs[nt][1]);
            atomicAdd(sqO  + cc,     cq[nt][0]);
            atomicAdd(sqO  + cc + 1, cq[nt][1]);
        }
    }
}

// ================= FP16 HMMA GEMM (half A [M][K], half B n-major [NC][K]) ==========
#define SMEM_BYTES_H (4 * HA_TILE * 2 + 2048)   // 2 A-bufs + 2 B-bufs + BN = 43008

template <typename TC, bool FUSE_BN, bool SWAP>
__global__ __launch_bounds__(256, 2) void k_mma_h(
    const __half* __restrict__ A, const __half* __restrict__ Bt,
    TC* __restrict__ C, int M, int K, int NC,
    float* __restrict__ sumO, float* __restrict__ sqO,
    const float* __restrict__ aSum, const float* __restrict__ aSq,
    const float* __restrict__ aG, const float* __restrict__ aBt, float aInv)
{
    extern __shared__ char dsmRaw[];
    __half* AsB = (__half*)dsmRaw;
    __half* BsB = (__half*)(dsmRaw + 2 * HA_TILE * 2);
    float* scS = (float*)(dsmRaw + 4 * HA_TILE * 2);
    float* shS = scS + 256;

    const int tid = threadIdx.x;
    const int lane = tid & 31, warp = tid >> 5;
    const int group = lane >> 2, qt = lane & 3;
    const int warpM = warp & 1, warpN = warp >> 1;
    const int mBase = (SWAP ? blockIdx.y : blockIdx.x) * 128;
    const int nBase = (SWAP ? blockIdx.x : blockIdx.y) * 128;
    const int nk = K >> 5;

    if (FUSE_BN) {
        if (tid < K) {
            float mean = aSum[tid] * aInv;
            float var  = aSq[tid] * aInv - mean * mean;
            float s = aG[tid] * rsqrtf(var + 1e-5f);
            scS[tid] = s; shS[tid] = aBt[tid] - mean * s;
        }
        __syncthreads();
    }

    const int arow = tid >> 2, akq = (tid & 3) << 3;  // halfs: TPR=4, RPI=64

    auto issue = [&](int i, int b) {
        const int k0 = i << 5;
        __half* As = AsB + b * HA_TILE;
        __half* Bs = BsB + b * HA_TILE;
#pragma unroll
        for (int it = 0; it < 2; it++) {
            int row = arow + it * 64;
            int gm = mBase + row;
            const __half* src = A + (size_t)(gm < M ? gm : 0) * K + k0 + akq;
            cpasync16(As + row * HSTR + akq, src, gm < M ? 16 : 0);
        }
#pragma unroll
        for (int it = 0; it < 2; it++) {
            int row = arow + it * 64;
            const __half* src = Bt + (size_t)(nBase + row) * K + k0 + akq;
            cpasync16(Bs + row * HSTR + akq, src, 16);
        }
        cpasync_commit();
    };

    float acc[4][4][4];
#pragma unroll
    for (int mt = 0; mt < 4; mt++)
#pragma unroll
        for (int nt = 0; nt < 4; nt++)
#pragma unroll
            for (int i = 0; i < 4; i++) acc[mt][nt][i] = 0.0f;

    issue(0, 0);
    for (int i = 0; i < nk; i++) {
        if (i + 1 < nk) { issue(i + 1, (i + 1) & 1); cpasync_wait<1>(); }
        else            { cpasync_wait<0>(); }
        __syncthreads();
        const __half* As = AsB + (i & 1) * HA_TILE;
        const __half* Bs = BsB + (i & 1) * HA_TILE;
        const int k0 = i << 5;
#pragma unroll
        for (int ks = 0; ks < 2; ks++) {
            const int kb = ks * 16 + 2 * qt;
            unsigned af[4][4], bf[4][2];
            float sc0, sh0, sc1, sh1, sc8, sh8, sc9, sh9;
            if (FUSE_BN) {
                int g = k0 + kb;
                sc0 = scS[g];     sh0 = shS[g];
                sc1 = scS[g + 1]; sh1 = shS[g + 1];
                sc8 = scS[g + 8]; sh8 = shS[g + 8];
                sc9 = scS[g + 9]; sh9 = shS[g + 9];
            }
#pragma unroll
            for (int mt = 0; mt < 4; mt++) {
                int r = warpM * 64 + mt * 16 + group;
                const __half* p0 = As + r * HSTR + kb;
                const __half* p1 = As + (r + 8) * HSTR + kb;
                if (FUSE_BN) {
                    float2 v0 = __half22float2(*(const __half2*)p0);
                    float2 v1 = __half22float2(*(const __half2*)p1);
                    float2 v2 = __half22float2(*(const __half2*)(p0 + 8));
                    float2 v3 = __half22float2(*(const __half2*)(p1 + 8));
                    af[mt][0] = h2u(__floats2half2_rn(
                        fmaxf(fmaf(v0.x, sc0, sh0), 0.f), fmaxf(fmaf(v0.y, sc1, sh1), 0.f)));
                    af[mt][1] = h2u(__floats2half2_rn(
                        fmaxf(fmaf(v1.x, sc0, sh0), 0.f), fmaxf(fmaf(v1.y, sc1, sh1), 0.f)));
                    af[mt][2] = h2u(__floats2half2_rn(
                        fmaxf(fmaf(v2.x, sc8, sh8), 0.f), fmaxf(fmaf(v2.y, sc9, sh9), 0.f)));
                    af[mt][3] = h2u(__floats2half2_rn(
                        fmaxf(fmaf(v3.x, sc8, sh8), 0.f), fmaxf(fmaf(v3.y, sc9, sh9), 0.f)));
                } else {
                    af[mt][0] = *(const unsigned*)p0;
                    af[mt][1] = *(const unsigned*)p1;
                    af[mt][2] = *(const unsigned*)(p0 + 8);
                    af[mt][3] = *(const unsigned*)(p1 + 8);
                }
            }
#pragma unroll
            for (int nt = 0; nt < 4; nt++) {
                int cb = warpN * 32 + nt * 8 + group;
                const __half* q = Bs + cb * HSTR + kb;
                bf[nt][0] = *(const unsigned*)q;
                bf[nt][1] = *(const unsigned*)(q + 8);
            }
#pragma unroll
            for (int mt = 0; mt < 4; mt++)
#pragma unroll
                for (int nt = 0; nt < 4; nt++)
                    MMA_F16(acc[mt][nt], af[mt], bf[nt]);
        }
        __syncthreads();
    }

    // epilogue: store + BN stats (on stored values)
    float cs[4][2], cq[4][2];
#pragma unroll
    for (int nt = 0; nt < 4; nt++) { cs[nt][0] = cs[nt][1] = 0.f; cq[nt][0] = cq[nt][1] = 0.f; }
#pragma unroll
    for (int mt = 0; mt < 4; mt++) {
        int r0 = mBase + warpM * 64 + mt * 16 + group;
        int r1 = r0 + 8;
#pragma unroll
        for (int nt = 0; nt < 4; nt++) {
            int cc = nBase + warpN * 32 + nt * 8 + 2 * qt;
            float x0, x1;
            if (r0 < M) {
                st2(C, (size_t)r0 * NC + cc, acc[mt][nt][0], acc[mt][nt][1], x0, x1);
                cs[nt][0] += x0; cs[nt][1] += x1;
                cq[nt][0] += x0 * x0; cq[nt][1] += x1 * x1;
            }
            if (r1 < M) {
                st2(C, (size_t)r1 * NC + cc, acc[mt][nt][2], acc[mt][nt][3], x0, x1);
                cs[nt][0] += x0; cs[nt][1] += x1;
                cq[nt][0] += x0 * x0; cq[nt][1] += x1 * x1;
            }
        }
    }
    if (sumO) {
#pragma unroll
        for (int off = 4; off < 32; off <<= 1) {
#pragma unroll
            for (int nt = 0; nt < 4; nt++) {
#pragma unroll
                for (int p = 0; p < 2; p++) {
                    cs[nt][p] += __shfl_xor_sync(0xffffffffu, cs[nt][p], off);
                    cq[nt][p] += __shfl_xor_sync(0xffffffffu, cq[nt][p], off);
                }
            }
        }
        if (group == 0) {
#pragma unroll
            for (int nt = 0; nt < 4; nt++) {
                int cc = nBase + warpN * 32 + nt * 8 + 2 * qt;
                atomicAdd(sumO + cc,     cs[nt][0]);
                atomicAdd(sumO + cc + 1, cs[nt][1]);
                atomicAdd(sqO  + cc,     cq[nt][0]);
                atomicAdd(sqO  + cc + 1, cq[nt][1]);
            }
        }
    }
}

// CSR gather: nin[n] = e11*nr[n] + sum_entries[(2+eps12)*h_r + h_sib]
__global__ void k_gather_nin(const float* __restrict__ nr,
                             const float* __restrict__ g, const float* __restrict__ b,
                             const float* __restrict__ eps12p,
                             const float* __restrict__ eps11p) {
    int n = blockIdx.x;
    int c = threadIdx.x;
    float mean = s_sum[c] * (1.0f / TE);
    float var  = s_sq[c]  * (1.0f / TE) - mean * mean;
    float sc = g[c] * rsqrtf(var + 1e-5f);
    float sh = b[c] - mean * sc;
    float cf = 2.0f + *eps12p;
    float e11 = 1.0f + *eps11p;
    int beg = s_rowptr[n], end = s_rowptr[n + 1];
    float acc = 0.f;
    for (int j = beg; j < end; j++) {
        int r = s_csr[j];
        int sIb = r ^ 1;
        float hr = fmaxf(__half2float(s_pre1[(size_t)r  * 128 + c]) * sc + sh, 0.f);
        float hs = fmaxf(__half2float(s_pre1[(size_t)sIb * 128 + c]) * sc + sh, 0.f);
        acc += cf * hr + hs;
    }
    s_nin[(size_t)n * 128 + c] = __float2half_rn(e11 * nr[(size_t)n * 128 + c] + acc);
}

__global__ void k_ein(const float* __restrict__ er, const float* __restrict__ nr,
                      const float* __restrict__ eps2p) {
    int c = threadIdx.x & 63;
    int eo = threadIdx.x >> 6;
    float e2 = 1.0f + *eps2p;
    float e2h = 0.5f * e2;
    const float2* er2 = (const float2*)er;
    const float2* nr2 = (const float2*)nr;
    __half2* ein = (__half2*)s_ein;
    for (int e = blockIdx.x * 2 + eo; e < NE; e += gridDim.x * 2) {
        int u = s_u[e], v = s_v[e];
        float2 a = er2[(size_t)(2 * e) * 64 + c];
        float2 bq = er2[(size_t)(2 * e + 1) * 64 + c];
        float2 p = nr2[(size_t)u * 64 + c];
        float2 q = nr2[(size_t)v * 64 + c];
        __half2 fh = __floats2half2_rn(e2h * (a.x + bq.x) + p.x + q.x,
                                       e2h * (a.y + bq.y) + p.y + q.y);
        size_t r0 = (size_t)(2 * e) * 128 + c, r1 = (size_t)(2 * e + 1) * 128 + c;
        ein[r0] = fh;
        ein[r1] = fh;
        ein[r0 + 64] = __floats2half2_rn(e2 * a.x + p.x,  e2 * a.y + p.y);
        ein[r1 + 64] = __floats2half2_rn(e2 * bq.x + q.x, e2 * bq.y + q.y);
    }
}

// dst(fp32) = relu(src(half)*scale + shift); BN coefs precomputed in smem (kills MUFU)
__global__ void k_bnapplyh(const __half2* __restrict__ src, float2* __restrict__ dst,
                           int rows,
                           const float* __restrict__ sum, const float* __restrict__ sq,
                           const float* __restrict__ g, const float* __restrict__ b,
                           float inv) {
    __shared__ float scS[128], shS[128];
    int t = threadIdx.x;
    if (t < 128) {
        float m = sum[t] * inv;
        float v = sq[t] * inv - m * m;
        float s = g[t] * rsqrtf(v + 1e-5f);
        scS[t] = s;
        shS[t] = b[t] - m * s;
    }
    __syncthreads();
    size_t n = (size_t)rows * 64;
    size_t stride = (size_t)gridDim.x * blockDim.x;
    for (size_t i = (size_t)blockIdx.x * blockDim.x + t; i < n; i += stride) {
        int c = (int)(i & 63) << 1;
        float2 v = __half22float2(src[i]);
        float o0 = fmaxf(fmaf(v.x, scS[c],     shS[c]),     0.f);
        float o1 = fmaxf(fmaf(v.y, scS[c + 1], shS[c + 1]), 0.f);
        dst[i] = make_float2(o0, o1);
    }
}

// ---------------- launch ----------------
extern "C" void kernel_launch(void* const* d_in, const int* in_sizes, int n_in,
                              void* d_out, int out_size) {
    const float* nr      = (const float*)d_in[0];
    const float* er      = (const float*)d_in[1];
    const void*  ei      = d_in[2];
    const float* lift_w1 = (const float*)d_in[3];
    const float* lift_g1 = (const float*)d_in[4];
    const float* lift_b1 = (const float*)d_in[5];
    const float* lift_w2 = (const float*)d_in[6];
    const float* lift_g2 = (const float*)d_in[7];
    const float* lift_b2 = (const float*)d_in[8];
    const float* lvl1_w  = (const float*)d_in[9];
    const float* lvl1_g  = (const float*)d_in[10];
    const float* lvl1_b  = (const float*)d_in[11];
    const float* lvl2_w1 = (const float*)d_in[12];
    const float* lvl2_g1 = (const float*)d_in[13];
    const float* lvl2_b1 = (const float*)d_in[14];
    const float* lvl2_w2 = (const float*)d_in[15];
    const float* lvl2_g2 = (const float*)d_in[16];
    const float* lvl2_b2 = (const float*)d_in[17];
    const float* eps11   = (const float*)d_in[18];
    const float* eps12   = (const float*)d_in[19];
    const float* eps2    = (const float*)d_in[20];

    float* out_node = (float*)d_out;
    float* out_edge = out_node + (size_t)NN * HH;

    __half *p_a0, *p_a1, *p_nin, *p_np1, *p_np2, *p_ein, *p_ep1, *p_ep2, *p_pre1;
    __half *p_wnp1, *p_wnp2, *p_wep1, *p_wep2, *p_wl1;
    float *p_sum, *p_sq;
    cudaGetSymbolAddress((void**)&p_a0,  s_a0);
    cudaGetSymbolAddress((void**)&p_a1,  s_a1);
    cudaGetSymbolAddress((void**)&p_pre1, s_pre1);
    cudaGetSymbolAddress((void**)&p_nin, s_nin);
    cudaGetSymbolAddress((void**)&p_np1, s_np1);
    cudaGetSymbolAddress((void**)&p_np2, s_np2);
    cudaGetSymbolAddress((void**)&p_ein, s_ein);
    cudaGetSymbolAddress((void**)&p_ep1, s_ep1);
    cudaGetSymbolAddress((void**)&p_ep2, s_ep2);
    cudaGetSymbolAddress((void**)&p_sum, s_sum);
    cudaGetSymbolAddress((void**)&p_sq,  s_sq);
    cudaGetSymbolAddress((void**)&p_wnp1, w_np1h);
    cudaGetSymbolAddress((void**)&p_wnp2, w_np2h);
    cudaGetSymbolAddress((void**)&p_wep1, w_ep1h);
    cudaGetSymbolAddress((void**)&p_wep2, w_ep2h);
    cudaGetSymbolAddress((void**)&p_wl1,  w_l1h);

    static cudaStream_t s_edge = nullptr, s_csrS = nullptr;
    static cudaEvent_t ev_root = nullptr, ev_dec = nullptr, ev_wp = nullptr,
                       ev_edge = nullptr, ev_csr = nullptr;
    static int smem_set = 0;
    if (!smem_set) {
        cudaFuncSetAttribute((const void*)k_mma_fh,
                             cudaFuncAttributeMaxDynamicSharedMemorySize, SMEM_BYTES_FH);
        cudaFuncSetAttribute((const void*)k_mma_pre1,
                             cudaFuncAttributeMaxDynamicSharedMemorySize, SMEM_BYTES_FH);
        cudaFuncSetAttribute((const void*)k_mma_h<__half, false, true>,
                             cudaFuncAttributeMaxDynamicSharedMemorySize, SMEM_BYTES_H);
        cudaFuncSetAttribute((const void*)k_mma_h<__half, true, false>,
                             cudaFuncAttributeMaxDynamicSharedMemorySize, SMEM_BYTES_H);
        cudaStreamCreateWithFlags(&s_edge, cudaStreamNonBlocking);
        cudaStreamCreateWithFlags(&s_csrS, cudaStreamNonBlocking);
        cudaEventCreateWithFlags(&ev_root, cudaEventDisableTiming);
        cudaEventCreateWithFlags(&ev_dec,  cudaEventDisableTiming);
        cudaEventCreateWithFlags(&ev_wp,   cudaEventDisableTiming);
        cudaEventCreateWithFlags(&ev_edge, cudaEventDisableTiming);
        cudaEventCreateWithFlags(&ev_csr,  cudaEventDisableTiming);
        smem_set = 1;
    }

    const int GN  = (NN + 127) / 128;  // 157
    const int GTE = TE / 128;          // 2500

    // -------- root fork: side streams must join capture via event-wait --------
    cudaEventRecord(ev_root, 0);
    cudaStreamWaitEvent(s_csrS, ev_root, 0);

    // stream 0: index decode          s_csrS: zero + weight prep (parallel)
    k_detect<<<1, 32>>>((const int*)ei);
    k_decode<<<(NE + 255) / 256, 256>>>(ei);
    cudaEventRecord(ev_dec, 0);

    k_zero<<<(NN + 255) / 256, 256, 0, s_csrS>>>();
    k_wprep<<<256, 256, 0, s_csrS>>>(lvl2_w1, lvl2_w2, lift_w1, lift_w2, lvl1_w);
    cudaEventRecord(ev_wp, s_csrS);

    // CSR build on s_csrS (needs decode)
    cudaStreamWaitEvent(s_csrS, ev_dec, 0);
    k_hist<<<(NE + 255) / 256, 256, 0, s_csrS>>>();
    k_scan<<<1, 1024, 0, s_csrS>>>();
    k_place<<<(NE + 255) / 256, 256, 0, s_csrS>>>();
    cudaEventRecord(ev_csr, s_csrS);

    // -------- edge chain (s_edge) --------
    cudaStreamWaitEvent(s_edge, ev_dec, 0);
    k_ein<<<2048, 128, 0, s_edge>>>(er, nr, eps2);
    cudaStreamWaitEvent(s_edge, ev_wp, 0);
    k_mma_h<__half, false, true><<<dim3(2, GTE), 256, SMEM_BYTES_H, s_edge>>>(
        p_ein, p_wep1, p_ep1, TE, 256, 256,
        p_sum + 768, p_sq + 768, nullptr, nullptr, nullptr, nullptr, 0.f);
    k_mma_h<__half, true, false><<<dim3(GTE, 1), 256, SMEM_BYTES_H, s_edge>>>(
        p_ep1, p_wep2, p_ep2, TE, 256, 128,
        p_sum + 1024, p_sq + 1024,
        p_sum + 768, p_sq + 768, lift_g1, lift_b1, 1.0f / TE);
    k_bnapplyh<<<4096, 256, 0, s_edge>>>((const __half2*)p_ep2, (float2*)out_edge, TE,
                              p_sum + 1024, p_sq + 1024, lift_g2, lift_b2, 1.0f / TE);
    cudaEventRecord(ev_edge, s_edge);

    // -------- node chain (stream 0) --------
    cudaStreamWaitEvent(0, ev_wp, 0);
    k_mma_fh<<<dim3(GN, 1), 256, SMEM_BYTES_FH>>>(nr, p_wl1,         p_a0, NN, 128, 128);
    k_mma_fh<<<dim3(GN, 1), 256, SMEM_BYTES_FH>>>(nr, p_wl1 + 16384, p_a1, NN, 128, 128);
    // pre1 = er@W2c + a0[u]+a0[v]+a1[atom], fused epilogue; stats slot 0
    k_mma_pre1<<<dim3(GTE, 1), 256, SMEM_BYTES_FH>>>(er, p_wl1 + 2 * 16384, p_pre1,
                                                     p_sum, p_sq);

    cudaStreamWaitEvent(0, ev_csr, 0);
    k_gather_nin<<<NN, 128>>>(nr, lvl1_g, lvl1_b, eps12, eps11);  // BN+aggregate+nin fused

    k_mma_h<__half, false, true><<<dim3(2, GN), 256, SMEM_BYTES_H>>>(
        p_nin, p_wnp1, p_np1, NN, 128, 256,
        p_sum + 256, p_sq + 256, nullptr, nullptr, nullptr, nullptr, 0.f);
    k_mma_h<__half, true, false><<<dim3(GN, 1), 256, SMEM_BYTES_H>>>(
        p_np1, p_wnp2, p_np2, NN, 256, 128,
        p_sum + 512, p_sq + 512,
        p_sum + 256, p_sq + 256, lvl2_g1, lvl2_b1, 1.0f / NN);
    k_bnapplyh<<<2048, 256>>>((const __half2*)p_np2, (float2*)out_node, NN,
                              p_sum + 512, p_sq + 512, lvl2_g2, lvl2_b2, 1.0f / NN);

    // -------- join --------
    cudaStreamWaitEvent(0, ev_edge, 0);
}